// round 1
// baseline (speedup 1.0000x reference)
#include <cuda_runtime.h>

// ConvTranspose2D: x(256,128,128) fp32, W(128,256,4,4) fp32, b(128) fp32
// out(128,256,256) fp32.
// stride=2, kernel=4, effective pad=2 on the dilated input (lhs_dilation=2).
//
// Parity decomposition: out[co, 2i+ph, 2j+pw] =
//   b[co] + sum_ci sum_{a,b in {0,1}} W[co,ci,2a+ph,2b+pw] * x[ci, i-1+a+ph, j-1+b+pw]
// -> 4 independent implicit GEMMs, each M=128 (co), N=128*128 (i,j), K=1024 (ci*4).

#define C_IN   256
#define C_OUT  128
#define H_IN   128
#define W_IN   128
#define H_OUT  256
#define K_TOT  1024   // C_IN * 4 taps
#define BK     8
#define BN     128

// Repacked weights: [cls][k][co], k = ci*4 + (a*2+b). 4*1024*128 floats = 2MB.
__device__ float g_Wp[4 * K_TOT * C_OUT];

__global__ void repack_w_kernel(const float* __restrict__ Wg) {
    int idx = blockIdx.x * blockDim.x + threadIdx.x;
    if (idx >= 4 * K_TOT * C_OUT) return;
    int cls = idx >> 17;          // / (1024*128)
    int rem = idx & 131071;
    int k   = rem >> 7;           // 0..1023
    int co  = rem & 127;
    int ci  = k >> 2;
    int t   = k & 3;
    int a   = t >> 1;
    int bb  = t & 1;
    int ph  = cls >> 1;
    int pw  = cls & 1;
    int kh  = 2 * a + ph;
    int kw  = 2 * bb + pw;
    // W layout: [co][ci][kh][kw] -> ((co*C_IN + ci)*4 + kh)*4 + kw
    g_Wp[idx] = Wg[((co * C_IN + ci) << 4) + (kh << 2) + kw];
}

__global__ __launch_bounds__(256, 2)
void convT_sgemm_kernel(const float* __restrict__ x,
                        const float* __restrict__ bias,
                        float* __restrict__ out) {
    const int cls = blockIdx.y;       // parity class 0..3
    const int i   = blockIdx.x;       // output parity-grid row 0..127
    const int ph  = cls >> 1;
    const int pw  = cls & 1;

    __shared__ float As[BK][C_OUT];   // weights tile  [k][co]
    __shared__ float Bs[BK][BN];      // input tile    [k][j]

    const int tid = threadIdx.x;
    const int ty  = tid >> 4;         // 0..15 -> co group of 8
    const int tx  = tid & 15;         // 0..15 -> j  group of 8

    float acc[8][8];
    #pragma unroll
    for (int r = 0; r < 8; r++)
        #pragma unroll
        for (int c = 0; c < 8; c++)
            acc[r][c] = 0.0f;

    const float* Wp = g_Wp + cls * (K_TOT * C_OUT);

    // Per-iteration global-load assignment
    const int lk = tid >> 5;          // 0..7: k-row within tile (one warp per row)
    const int lc = (tid & 31) << 2;   // 0..124: float4 base (co for A, j for B)

    for (int kt = 0; kt < K_TOT; kt += BK) {
        // --- A tile: coalesced float4 from repacked weights ---
        const float4 av = *reinterpret_cast<const float4*>(
            Wp + (kt + lk) * C_OUT + lc);
        *reinterpret_cast<float4*>(&As[lk][lc]) = av;

        // --- B tile: 4 scalars from x (contiguous row, shifted, edge zero-fill) ---
        const int k  = kt + lk;
        const int ci = k >> 2;
        const int t  = k & 3;
        const int a  = t >> 1;
        const int bq = t & 1;
        const int ih = i - 1 + a + ph;
        const bool row_ok = ((unsigned)ih < (unsigned)H_IN);
        const float* xrow = x + (ci * H_IN + ih) * W_IN;
        #pragma unroll
        for (int q = 0; q < 4; q++) {
            const int j  = lc + q;
            const int iw = j - 1 + bq + pw;
            Bs[lk][j] = (row_ok && (unsigned)iw < (unsigned)W_IN) ? xrow[iw] : 0.0f;
        }
        __syncthreads();

        // --- 8x8 register-blocked FMA ---
        #pragma unroll
        for (int kk = 0; kk < BK; kk++) {
            float af[8], bf[8];
            *reinterpret_cast<float4*>(&af[0]) = *reinterpret_cast<const float4*>(&As[kk][ty * 8]);
            *reinterpret_cast<float4*>(&af[4]) = *reinterpret_cast<const float4*>(&As[kk][ty * 8 + 4]);
            *reinterpret_cast<float4*>(&bf[0]) = *reinterpret_cast<const float4*>(&Bs[kk][tx * 8]);
            *reinterpret_cast<float4*>(&bf[4]) = *reinterpret_cast<const float4*>(&Bs[kk][tx * 8 + 4]);
            #pragma unroll
            for (int r = 0; r < 8; r++)
                #pragma unroll
                for (int c = 0; c < 8; c++)
                    acc[r][c] = fmaf(af[r], bf[c], acc[r][c]);
        }
        __syncthreads();
    }

    // --- Epilogue: add bias, scatter stride-2 stores ---
    const int oh = 2 * i + ph;
    #pragma unroll
    for (int r = 0; r < 8; r++) {
        const int co = ty * 8 + r;
        const float bv = bias[co];
        float* orow = out + ((size_t)co * H_OUT + oh) * H_OUT;
        #pragma unroll
        for (int c = 0; c < 8; c++) {
            const int j = tx * 8 + c;
            orow[2 * j + pw] = acc[r][c] + bv;
        }
    }
}

extern "C" void kernel_launch(void* const* d_in, const int* in_sizes, int n_in,
                              void* d_out, int out_size) {
    const float* x  = (const float*)d_in[0];   // 256*128*128
    const float* Wg = (const float*)d_in[1];   // 128*256*4*4
    const float* b  = (const float*)d_in[2];   // 128
    float* out = (float*)d_out;                // 128*256*256

    // 1) repack weights into per-class GEMM-friendly layout
    const int nrep = 4 * K_TOT * C_OUT;
    repack_w_kernel<<<(nrep + 255) / 256, 256>>>(Wg);

    // 2) 4 parity-class implicit GEMMs (grid: 128 i-rows x 4 classes)
    dim3 grid(H_IN, 4);
    convT_sgemm_kernel<<<grid, 256>>>(x, b, out);
}

// round 3
// speedup vs baseline: 3.4779x; 3.4779x over previous
#include <cuda_runtime.h>
#include <cstdint>

// ConvTranspose2D via 4 parity-class implicit GEMMs on mma.sync tf32 (HMMA).
// out[co, 2i+ph, 2j+pw] = b[co] + sum_{ci,a,b} W[co,ci,2a+ph,2b+pw] * x[ci,i-1+a+ph,j-1+b+pw]
// Per class: M=128 (co), N=128 per i-row (j), K=1024 (ci*4 taps). Grid 128x4.

#define C_IN   256
#define C_OUT  128
#define H_IN   128
#define W_IN   128
#define H_OUT  256
#define K_TOT  1024
#define NCHUNK 32          // 32 k per chunk

// A images: per (cls, chunk) 4096 floats in exact m16n8k8 A-fragment register
// order: idx = ((mt8*4 + ks)*32 + lane)*4 + reg. 2 MB total.
__device__ float g_Wimg[4 * NCHUNK * 4096];
// x pre-rounded to tf32 (round-to-nearest).
__device__ float g_xr[C_IN * H_IN * W_IN];

__global__ void prep_w(const float* __restrict__ Wg) {
    int idx = blockIdx.x * blockDim.x + threadIdx.x;
    if (idx >= 4 * K_TOT * C_OUT) return;
    int cls = idx >> 17;
    int rem = idx & 131071;
    int k   = rem >> 7;            // 0..1023
    int co  = rem & 127;
    int ci  = k >> 2;
    int a   = (k >> 1) & 1;
    int b   = k & 1;
    int ph  = cls >> 1, pw = cls & 1;
    float v = Wg[((co * C_IN + ci) << 4) + ((2 * a + ph) << 2) + (2 * b + pw)];
    float r; asm("cvt.rna.tf32.f32 %0, %1;" : "=f"(r) : "f"(v));
    int chunk = k >> 5, kl = k & 31;
    int ks = kl >> 3, kk = kl & 7;         // k8-step, col within frag
    int mt8 = co >> 4, rr = co & 15;       // m-tile, row within tile
    int lane = ((rr & 7) << 2) | (kk & 3);
    int reg  = ((kk >> 2) << 1) | (rr >> 3);
    g_Wimg[(cls * NCHUNK + chunk) * 4096 + ((mt8 * 4 + ks) * 32 + lane) * 4 + reg] = r;
}

__global__ void prep_x(const float* __restrict__ x) {
    int idx = blockIdx.x * blockDim.x + threadIdx.x;
    if (idx >= C_IN * H_IN * W_IN) return;
    float r; asm("cvt.rna.tf32.f32 %0, %1;" : "=f"(r) : "f"(x[idx]));
    g_xr[idx] = r;
}

__global__ __launch_bounds__(256, 2)
void convT_mma(const float* __restrict__ bias, float* __restrict__ out) {
    __shared__ float As[4096];    // A frag image, 16KB
    __shared__ float Bs0[2048];   // B frag plane k%8<4, 8KB
    __shared__ float Bs1[2048];   // B frag plane k%8>=4, 8KB

    const int cls = blockIdx.y;
    const int i   = blockIdx.x;
    const int ph  = cls >> 1, pw = cls & 1;
    const int tid = threadIdx.x;
    const int wid = tid >> 5, lid = tid & 31;
    const int wm  = wid >> 2;     // 0..1 -> co base wm*64
    const int wn  = wid & 3;      // 0..3 -> j  base wn*32

    float acc[4][4][4];
    #pragma unroll
    for (int mt = 0; mt < 4; mt++)
        #pragma unroll
        for (int nt = 0; nt < 4; nt++)
            #pragma unroll
            for (int q = 0; q < 4; q++) acc[mt][nt][q] = 0.0f;

    const float* Aimg = g_Wimg + (size_t)cls * NCHUNK * 4096;

    float4 areg[4];
    float  breg[4][4];   // [o][t], t = k&3 for this warp's k-group

    // ---- staging: LDGs for chunk c into regs ----
    // warp g covers k_local = g*4 + t (t=0..3): ci = c*8 + g, a = t>>1, b = t&1.
    #define STAGE(c)                                                           \
    {                                                                          \
        const float4* asrc = (const float4*)(Aimg + (c) * 4096);               \
        _Pragma("unroll")                                                      \
        for (int u = 0; u < 4; u++) areg[u] = asrc[tid + (u << 8)];            \
        const int ci = (c) * 8 + wid;                                          \
        _Pragma("unroll")                                                      \
        for (int p = 0; p < 2; p++) {                                          \
            const int ih = i - 1 + p + ph;                                     \
            const bool rok = (unsigned)ih < (unsigned)H_IN;                    \
            const float* row = g_xr + (ci * H_IN + ih) * W_IN;                 \
            _Pragma("unroll")                                                  \
            for (int o = 0; o < 4; o++) {                                      \
                const int jm = lid + 32 * o - 1 + pw;                          \
                breg[o][p * 2 + 0] =                                           \
                    (rok && (unsigned)jm < (unsigned)W_IN) ? row[jm] : 0.0f;   \
                breg[o][p * 2 + 1] =                                           \
                    (rok && (unsigned)(jm + 1) < (unsigned)W_IN) ? row[jm + 1] \
                                                                 : 0.0f;       \
            }                                                                  \
        }                                                                      \
    }

    STAGE(0);

    for (int c = 0; c < NCHUNK; c++) {
        __syncthreads();   // previous compute done with smem

        // ---- commit staged regs to smem ----
        #pragma unroll
        for (int u = 0; u < 4; u++) ((float4*)As)[tid + (u << 8)] = areg[u];
        {
            float* plane = (wid & 1) ? Bs1 : Bs0;
            const int ks = wid >> 1;
            #pragma unroll
            for (int o = 0; o < 4; o++) {
                const int j = lid + 32 * o;
                *(float4*)&plane[((j >> 3) * 4 + ks) * 32 + (j & 7) * 4] =
                    make_float4(breg[o][0], breg[o][1], breg[o][2], breg[o][3]);
            }
        }
        __syncthreads();

        if (c + 1 < NCHUNK) STAGE(c + 1);   // overlap LDGs with compute

        // ---- compute: 4 k8-steps x 16 mma ----
        #pragma unroll
        for (int ks = 0; ks < 4; ks++) {
            float4 af[4];
            #pragma unroll
            for (int mt = 0; mt < 4; mt++)
                af[mt] = ((const float4*)As)[((wm * 4 + mt) * 4 + ks) * 32 + lid];
            float b0[4], b1[4];
            #pragma unroll
            for (int nt = 0; nt < 4; nt++) {
                b0[nt] = Bs0[((wn * 4 + nt) * 4 + ks) * 32 + lid];
                b1[nt] = Bs1[((wn * 4 + nt) * 4 + ks) * 32 + lid];
            }
            #pragma unroll
            for (int mt = 0; mt < 4; mt++)
                #pragma unroll
                for (int nt = 0; nt < 4; nt++)
                    asm volatile(
                        "mma.sync.aligned.m16n8k8.row.col.f32.tf32.tf32.f32 "
                        "{%0,%1,%2,%3}, {%4,%5,%6,%7}, {%8,%9}, {%0,%1,%2,%3};"
                        : "+f"(acc[mt][nt][0]), "+f"(acc[mt][nt][1]),
                          "+f"(acc[mt][nt][2]), "+f"(acc[mt][nt][3])
                        : "r"(__float_as_uint(af[mt].x)), "r"(__float_as_uint(af[mt].y)),
                          "r"(__float_as_uint(af[mt].z)), "r"(__float_as_uint(af[mt].w)),
                          "r"(__float_as_uint(b0[nt])), "r"(__float_as_uint(b1[nt])));
        }
    }

    // ---- epilogue: bias + stride-2 scatter ----
    const int oh = 2 * i + ph;
    #pragma unroll
    for (int mt = 0; mt < 4; mt++) {
        const int co0 = wm * 64 + mt * 16 + (lid >> 2);
        const int co1 = co0 + 8;
        const float bv0 = bias[co0];
        const float bv1 = bias[co1];
        float* r0 = out + ((size_t)co0 * H_OUT + oh) * H_OUT + pw;
        float* r1 = out + ((size_t)co1 * H_OUT + oh) * H_OUT + pw;
        #pragma unroll
        for (int nt = 0; nt < 4; nt++) {
            const int j0 = wn * 32 + nt * 8 + 2 * (lid & 3);
            r0[2 * j0]       = acc[mt][nt][0] + bv0;
            r0[2 * (j0 + 1)] = acc[mt][nt][1] + bv0;
            r1[2 * j0]       = acc[mt][nt][2] + bv1;
            r1[2 * (j0 + 1)] = acc[mt][nt][3] + bv1;
        }
    }
}

extern "C" void kernel_launch(void* const* d_in, const int* in_sizes, int n_in,
                              void* d_out, int out_size) {
    const float* x  = (const float*)d_in[0];   // 256*128*128
    const float* Wg = (const float*)d_in[1];   // 128*256*4*4
    const float* b  = (const float*)d_in[2];   // 128
    float* out = (float*)d_out;                // 128*256*256

    prep_w<<<(4 * K_TOT * C_OUT + 255) / 256, 256>>>(Wg);
    prep_x<<<(C_IN * H_IN * W_IN + 255) / 256, 256>>>(x);

    dim3 grid(H_IN, 4);
    convT_mma<<<grid, 256>>>(b, out);
}

// round 4
// speedup vs baseline: 3.7408x; 1.0756x over previous
#include <cuda_runtime.h>
#include <cstdint>

// ConvTranspose2D via 4 parity-class implicit GEMMs on mma.sync tf32 (HMMA).
// out[co, 2i+ph, 2j+pw] = b[co] + sum_{ci,a,b} W[co,ci,2a+ph,2b+pw] * x[ci,i-1+a+ph,j-1+b+pw]
// Per class: M=128 (co), N=128 per i-row (j), K=1024 (ci*4 taps). Grid 128x4.

#define C_IN   256
#define C_OUT  128
#define H_IN   128
#define W_IN   128
#define H_OUT  256
#define K_TOT  1024
#define NCHUNK 32
#define XP_H   130
#define XP_W   132

// A images: per (cls, chunk) 4096 floats in exact m16n8k8 A-fragment register
// order: idx = ((mt8*4 + ks)*32 + lane)*4 + reg. 2 MB total.
__device__ float g_Wimg[4 * NCHUNK * 4096];
// Zero-padded, tf32-rounded x: [ci][ih+1 : 0..129][iw+1 : 0..131]. ~17.6 MB.
__device__ float g_xp[C_IN * XP_H * XP_W];

__global__ void prep_w(const float* __restrict__ Wg) {
    int idx = blockIdx.x * blockDim.x + threadIdx.x;
    if (idx >= 4 * K_TOT * C_OUT) return;
    int cls = idx >> 17;
    int rem = idx & 131071;
    int k   = rem >> 7;            // 0..1023
    int co  = rem & 127;
    int ci  = k >> 2;
    int a   = (k >> 1) & 1;
    int b   = k & 1;
    int ph  = cls >> 1, pw = cls & 1;
    float v = Wg[((co * C_IN + ci) << 4) + ((2 * a + ph) << 2) + (2 * b + pw)];
    float r; asm("cvt.rna.tf32.f32 %0, %1;" : "=f"(r) : "f"(v));
    int chunk = k >> 5, kl = k & 31;
    int ks = kl >> 3, kk = kl & 7;
    int mt8 = co >> 4, rr = co & 15;
    int lane = ((rr & 7) << 2) | (kk & 3);
    int reg  = ((kk >> 2) << 1) | (rr >> 3);
    g_Wimg[(cls * NCHUNK + chunk) * 4096 + ((mt8 * 4 + ks) * 32 + lane) * 4 + reg] = r;
}

__global__ void prep_xpad(const float* __restrict__ x) {
    int idx = blockIdx.x * blockDim.x + threadIdx.x;
    if (idx >= C_IN * XP_H * XP_W) return;
    int ci  = idx / (XP_H * XP_W);
    int rem = idx % (XP_H * XP_W);
    int ih  = rem / XP_W - 1;
    int iw  = rem % XP_W - 1;
    float v = 0.0f;
    if ((unsigned)ih < (unsigned)H_IN && (unsigned)iw < (unsigned)W_IN) {
        float t = x[(ci * H_IN + ih) * W_IN + iw];
        asm("cvt.rna.tf32.f32 %0, %1;" : "=f"(v) : "f"(t));
    }
    g_xp[idx] = v;
}

__device__ __forceinline__ uint32_t smem_u32(const void* p) {
    uint32_t a;
    asm("{ .reg .u64 t; cvta.to.shared.u64 t, %1; cvt.u32.u64 %0, t; }" : "=r"(a) : "l"(p));
    return a;
}

__global__ __launch_bounds__(256, 2)
void convT_mma(const float* __restrict__ bias, float* __restrict__ out) {
    __shared__ float As[2][4096];    // A frag images (double buffered), 32KB
    __shared__ float Bs[2][2][2048]; // B frag planes [buf][k%8 half], 32KB

    const int cls = blockIdx.y;
    const int i   = blockIdx.x;
    const int ph  = cls >> 1, pw = cls & 1;
    const int tid = threadIdx.x;
    const int wid = tid >> 5, lid = tid & 31;
    const int wm  = wid >> 2;     // 0..1 -> co base wm*64
    const int wn  = wid & 3;      // 0..3 -> j  base wn*32

    float acc[4][4][4];
    #pragma unroll
    for (int mt = 0; mt < 4; mt++)
        #pragma unroll
        for (int nt = 0; nt < 4; nt++)
            #pragma unroll
            for (int q = 0; q < 4; q++) acc[mt][nt][q] = 0.0f;

    const float* Aimg = g_Wimg + (size_t)cls * NCHUNK * 4096;
    const uint32_t sA0 = smem_u32(&As[0][0]);
    const uint32_t sA1 = smem_u32(&As[1][0]);

    // B stage base: ih+1 = i + p + ph, iw+1 = lid + 32*o + pw (always in-bounds).
    const float* xbase = g_xp + (size_t)(i + ph) * XP_W + (lid + pw);

    float breg[4][4];   // [o][t]

    // A: global->shared async copy, 4 x 16B per thread.
    #define CPA(c, sbuf)                                                       \
    {                                                                          \
        const float* src = Aimg + (c) * 4096 + tid * 4;                        \
        uint32_t dst = (sbuf) + tid * 16;                                      \
        _Pragma("unroll")                                                      \
        for (int u = 0; u < 4; u++)                                            \
            asm volatile("cp.async.ca.shared.global [%0], [%1], 16;"           \
                         :: "r"(dst + u * 4096), "l"(src + u * 1024));         \
        asm volatile("cp.async.commit_group;");                                \
    }

    // B: unpredicated LDGs from padded image into regs.
    // warp wid covers k_local = wid*4 + t: ci = c*8 + wid, a = t>>1, b = t&1.
    #define STAGEB(c)                                                          \
    {                                                                          \
        const float* rb = xbase + ((size_t)((c) * 8 + wid) * XP_H) * XP_W;     \
        _Pragma("unroll")                                                      \
        for (int p = 0; p < 2; p++) {                                          \
            const float* row = rb + p * XP_W;                                  \
            _Pragma("unroll")                                                  \
            for (int o = 0; o < 4; o++) {                                      \
                breg[o][p * 2 + 0] = row[32 * o];                              \
                breg[o][p * 2 + 1] = row[32 * o + 1];                          \
            }                                                                  \
        }                                                                      \
    }

    #define STOREB(buf)                                                        \
    {                                                                          \
        float* plane = Bs[buf][wid & 1];                                       \
        const int ks = wid >> 1;                                               \
        _Pragma("unroll")                                                      \
        for (int o = 0; o < 4; o++) {                                          \
            const int j = lid + 32 * o;                                        \
            *(float4*)&plane[((j >> 3) * 4 + ks) * 32 + (j & 7) * 4] =         \
                make_float4(breg[o][0], breg[o][1], breg[o][2], breg[o][3]);   \
        }                                                                      \
    }

    // ---- prologue: fill buffer 0 ----
    CPA(0, sA0);
    STAGEB(0);
    asm volatile("cp.async.wait_group 0;" ::: "memory");
    STOREB(0);
    __syncthreads();

    int p = 0;
    for (int c = 0; c < NCHUNK; c++) {
        const int q = p ^ 1;
        if (c + 1 < NCHUNK) {
            CPA(c + 1, p ? sA0 : sA1);
            STAGEB(c + 1);
        }

        // ---- compute chunk c from buffer p ----
        const float* Ab  = As[p];
        const float* Bp0 = Bs[p][0];
        const float* Bp1 = Bs[p][1];
        #pragma unroll
        for (int ks = 0; ks < 4; ks++) {
            float4 af[4];
            #pragma unroll
            for (int mt = 0; mt < 4; mt++)
                af[mt] = ((const float4*)Ab)[((wm * 4 + mt) * 4 + ks) * 32 + lid];
            float b0[4], b1[4];
            #pragma unroll
            for (int nt = 0; nt < 4; nt++) {
                b0[nt] = Bp0[((wn * 4 + nt) * 4 + ks) * 32 + lid];
                b1[nt] = Bp1[((wn * 4 + nt) * 4 + ks) * 32 + lid];
            }
            #pragma unroll
            for (int mt = 0; mt < 4; mt++)
                #pragma unroll
                for (int nt = 0; nt < 4; nt++)
                    asm volatile(
                        "mma.sync.aligned.m16n8k8.row.col.f32.tf32.tf32.f32 "
                        "{%0,%1,%2,%3}, {%4,%5,%6,%7}, {%8,%9}, {%0,%1,%2,%3};"
                        : "+f"(acc[mt][nt][0]), "+f"(acc[mt][nt][1]),
                          "+f"(acc[mt][nt][2]), "+f"(acc[mt][nt][3])
                        : "r"(__float_as_uint(af[mt].x)), "r"(__float_as_uint(af[mt].y)),
                          "r"(__float_as_uint(af[mt].z)), "r"(__float_as_uint(af[mt].w)),
                          "r"(__float_as_uint(b0[nt])), "r"(__float_as_uint(b1[nt])));
        }

        if (c + 1 < NCHUNK) {
            asm volatile("cp.async.wait_group 0;" ::: "memory");
            STOREB(q);
            __syncthreads();
        }
        p = q;
    }

    // ---- epilogue: bias + stride-2 scatter ----
    const int oh = 2 * i + ph;
    #pragma unroll
    for (int mt = 0; mt < 4; mt++) {
        const int co0 = wm * 64 + mt * 16 + (lid >> 2);
        const int co1 = co0 + 8;
        const float bv0 = bias[co0];
        const float bv1 = bias[co1];
        float* r0 = out + ((size_t)co0 * H_OUT + oh) * H_OUT + pw;
        float* r1 = out + ((size_t)co1 * H_OUT + oh) * H_OUT + pw;
        #pragma unroll
        for (int nt = 0; nt < 4; nt++) {
            const int j0 = wn * 32 + nt * 8 + 2 * (lid & 3);
            r0[2 * j0]       = acc[mt][nt][0] + bv0;
            r0[2 * (j0 + 1)] = acc[mt][nt][1] + bv0;
            r1[2 * j0]       = acc[mt][nt][2] + bv1;
            r1[2 * (j0 + 1)] = acc[mt][nt][3] + bv1;
        }
    }
}

extern "C" void kernel_launch(void* const* d_in, const int* in_sizes, int n_in,
                              void* d_out, int out_size) {
    const float* x  = (const float*)d_in[0];   // 256*128*128
    const float* Wg = (const float*)d_in[1];   // 128*256*4*4
    const float* b  = (const float*)d_in[2];   // 128
    float* out = (float*)d_out;                // 128*256*256

    prep_w<<<(4 * K_TOT * C_OUT + 255) / 256, 256>>>(Wg);
    prep_xpad<<<(C_IN * XP_H * XP_W + 255) / 256, 256>>>(x);

    dim3 grid(H_IN, 4);
    convT_mma<<<grid, 256>>>(b, out);
}